// round 13
// baseline (speedup 1.0000x reference)
#include <cuda_runtime.h>
#include <cuda_fp16.h>

// Chebyshev (L-inf) pairwise distance: out[i,j] = max_d |A[i,d] - B[j,d]|
// A: [4096, 32] fp32, B: [4096, 32] fp32, out: [4096, 4096] fp32.
//
// R13: PIPE-MIX DISCRIMINATOR. Tile cols [0,64) use the fp16x2-over-d path
// (HSUB2 + HMNMX2, ~1 instr/elem*d); cols [64,128) use the fp32 path
// (add.rn.f32x2 packed subtract on fma + FMNMX|abs| on alu, 1.5 instr/elem*d).
// If fp16 SIMD is a separate shared unit (Model A), all three pipes run
// concurrently -> ~25-28us. If a ~2.7/cyc issue ceiling binds (Model B),
// this regresses to ~35us and fixes the session roofline at ~31us.
// Per-thread block: 4 rows x (4 fp16 cols + 4 fp32 cols).

constexpr int D  = 32;
constexpr int DP = D / 2;     // 16 d-pairs
constexpr int TI = 64;        // rows per CTA
constexpr int TJ = 128;       // cols per CTA (64 fp16 + 64 fp32)

__global__ __launch_bounds__(256, 3)
void cheby_kernel(const float* __restrict__ A, const float* __restrict__ B,
                  float* __restrict__ out, int M) {
    __shared__ __half2 Ah[DP][TI + 4];      // (A[bi+r][2dp], A[bi+r][2dp+1])
    __shared__ __half2 Bh[DP][64 + 4];      // cols 0..63, same d-pair packing
    __shared__ float   Adup[D][2 * TI + 4]; // (a, a) duplicated fp32
    __shared__ float   Bneg[D][64 + 4];     // -B for cols 64..127

    const int tid = threadIdx.x;
    const int bi  = blockIdx.y * TI;
    const int bj  = blockIdx.x * TJ;

    // A tile: 64 rows x 32 d = 512 float4; 256 threads x 2.
    #pragma unroll
    for (int k = 0; k < 2; k++) {
        int idx = tid + k * 256;
        int row = idx >> 3;                 // 0..63
        int dg  = (idx & 7) << 2;
        float4 v = *reinterpret_cast<const float4*>(A + (size_t)(bi + row) * D + dg);
        Ah[(dg >> 1) + 0][row] = __floats2half2_rn(v.x, v.y);
        Ah[(dg >> 1) + 1][row] = __floats2half2_rn(v.z, v.w);
        Adup[dg + 0][2*row] = v.x; Adup[dg + 0][2*row + 1] = v.x;
        Adup[dg + 1][2*row] = v.y; Adup[dg + 1][2*row + 1] = v.y;
        Adup[dg + 2][2*row] = v.z; Adup[dg + 2][2*row + 1] = v.z;
        Adup[dg + 3][2*row] = v.w; Adup[dg + 3][2*row + 1] = v.w;
    }
    // B tile: 128 rows x 32 d = 1024 float4; 256 threads x 4.
    #pragma unroll
    for (int k = 0; k < 4; k++) {
        int idx = tid + k * 256;
        int row = idx >> 3;                 // 0..127
        int dg  = (idx & 7) << 2;
        float4 v = *reinterpret_cast<const float4*>(B + (size_t)(bj + row) * D + dg);
        if (row < 64) {                     // fp16 region
            Bh[(dg >> 1) + 0][row] = __floats2half2_rn(v.x, v.y);
            Bh[(dg >> 1) + 1][row] = __floats2half2_rn(v.z, v.w);
        } else {                            // fp32 region, negated
            int c = row - 64;
            Bneg[dg + 0][c] = -v.x; Bneg[dg + 1][c] = -v.y;
            Bneg[dg + 2][c] = -v.z; Bneg[dg + 3][c] = -v.w;
        }
    }
    __syncthreads();

    const int tx = tid & 15;                // 16 x 4 cols per region
    const int ty = tid >> 4;                // 16 x 4 rows = 64
    const int ri = ty * 4;
    const int rj = tx * 4;

    __half2 acc16[4][4];                    // fp16 cols: lo/hi = even/odd d-phase
    float   acc32[4][4];                    // fp32 cols
    #pragma unroll
    for (int i = 0; i < 4; i++)
        #pragma unroll
        for (int j = 0; j < 4; j++) {
            acc16[i][j] = __float2half2_rn(0.0f);
            acc32[i][j] = 0.0f;
        }

    #pragma unroll 4
    for (int dp = 0; dp < DP; dp++) {
        // ---- fp16 half: 2 d's, 4 rows x 4 cols ----
        uint4 aq = *reinterpret_cast<const uint4*>(&Ah[dp][ri]);   // 4 h2, bcast
        uint4 bq = *reinterpret_cast<const uint4*>(&Bh[dp][rj]);   // 4 h2, 16B*tx
        const __half2 ha[4] = {
            *reinterpret_cast<__half2*>(&aq.x), *reinterpret_cast<__half2*>(&aq.y),
            *reinterpret_cast<__half2*>(&aq.z), *reinterpret_cast<__half2*>(&aq.w)};
        const __half2 hb[4] = {
            *reinterpret_cast<__half2*>(&bq.x), *reinterpret_cast<__half2*>(&bq.y),
            *reinterpret_cast<__half2*>(&bq.z), *reinterpret_cast<__half2*>(&bq.w)};
        #pragma unroll
        for (int i = 0; i < 4; i++)
            #pragma unroll
            for (int j = 0; j < 4; j++) {
                __half2 diff = __hsub2(ha[i], hb[j]);
                acc16[i][j] = __hmax2(acc16[i][j], __habs2(diff));
            }

        // ---- fp32 half: same 2 d's, 4 rows x 4 cols (cols 64+rj..) ----
        #pragma unroll
        for (int dd = 0; dd < 2; dd++) {
            int d = 2 * dp + dd;
            ulonglong2 ap0 = *reinterpret_cast<const ulonglong2*>(&Adup[d][2*ri]);
            ulonglong2 ap1 = *reinterpret_cast<const ulonglong2*>(&Adup[d][2*ri + 4]);
            ulonglong2 bp  = *reinterpret_cast<const ulonglong2*>(&Bneg[d][rj]);
            const unsigned long long ap[4] = {ap0.x, ap0.y, ap1.x, ap1.y};
            const unsigned long long bpp[2] = {bp.x, bp.y};
            #pragma unroll
            for (int i = 0; i < 4; i++)
                #pragma unroll
                for (int q = 0; q < 2; q++) {
                    unsigned long long s;
                    asm("add.rn.f32x2 %0, %1, %2;" : "=l"(s) : "l"(ap[i]), "l"(bpp[q]));
                    float lo, hi;
                    asm("mov.b64 {%0, %1}, %2;" : "=f"(lo), "=f"(hi) : "l"(s));
                    acc32[i][2*q + 0] = fmaxf(acc32[i][2*q + 0], fabsf(lo));
                    acc32[i][2*q + 1] = fmaxf(acc32[i][2*q + 1], fabsf(hi));
                }
        }
    }

    // Epilogue: two float4 stores per row (fp16 region cols bj+rj,
    // fp32 region cols bj+64+rj).
    #pragma unroll
    for (int i = 0; i < 4; i++) {
        float* po = out + (size_t)(bi + ri + i) * M + bj;
        float h0 = __half2float(__hmax(__low2half(acc16[i][0]), __high2half(acc16[i][0])));
        float h1 = __half2float(__hmax(__low2half(acc16[i][1]), __high2half(acc16[i][1])));
        float h2v = __half2float(__hmax(__low2half(acc16[i][2]), __high2half(acc16[i][2])));
        float h3 = __half2float(__hmax(__low2half(acc16[i][3]), __high2half(acc16[i][3])));
        *reinterpret_cast<float4*>(po + rj) = make_float4(h0, h1, h2v, h3);
        *reinterpret_cast<float4*>(po + 64 + rj) =
            make_float4(acc32[i][0], acc32[i][1], acc32[i][2], acc32[i][3]);
    }
}

extern "C" void kernel_launch(void* const* d_in, const int* in_sizes, int n_in,
                              void* d_out, int out_size) {
    const float* A = (const float*)d_in[0];
    const float* B = (const float*)d_in[1];
    float* out = (float*)d_out;
    int N = in_sizes[0] / D;   // 4096
    int M = in_sizes[1] / D;   // 4096
    dim3 grid(M / TJ, N / TI); // 32 x 64 = 2048 CTAs
    cheby_kernel<<<grid, 256>>>(A, B, out, M);
}

// round 14
// speedup vs baseline: 1.1635x; 1.1635x over previous
#include <cuda_runtime.h>
#include <cuda_fp16.h>

// Chebyshev (L-inf) pairwise distance: out[i,j] = max_d |A[i,d] - B[j,d]|
// A: [4096, 32] fp32, B: [4096, 32] fp32, out: [4096, 4096] fp32.
//
// R14: Model-B regime (hard ~2.7 warp-instr/cyc/SM issue ceiling, est. R13).
// Only lever left: instruction count. 16x4 per-thread block with d-pair
// fp16x2 packing -> per dp: 5 LDS.128 + 128 math = 95% math density.
// Operands alias the loaded uint4 regs directly (no copy MOVs).
// Total stream ~18.5M warp-instr vs 24M in R12 -> predict 26-29us.

constexpr int D  = 32;
constexpr int DP = D / 2;       // 16 d-pairs
constexpr int TI = 256;         // rows per CTA tile
constexpr int TJ = 64;          // cols per CTA tile

__global__ __launch_bounds__(256, 2)
void cheby_kernel(const float* __restrict__ A, const float* __restrict__ B,
                  float* __restrict__ out, int M) {
    __shared__ __half2 Ah[DP][TI + 4];  // Ah[dp][r] = (A[bi+r][2dp], A[bi+r][2dp+1])
    __shared__ __half2 Bh[DP][TJ + 4];  // Bh[dp][c] = (B[bj+c][2dp], B[bj+c][2dp+1])

    const int tid = threadIdx.x;
    const int bi  = blockIdx.y * TI;
    const int bj  = blockIdx.x * TJ;

    // A tile: 256 rows x 32 d = 2048 float4; 256 threads x 8.
    #pragma unroll
    for (int k = 0; k < 8; k++) {
        int idx = tid + k * 256;
        int row = idx & 255;            // walk rows fast, d-group slow
        int dg  = (idx >> 8) << 2;      // 0,4,...,28
        float4 v = *reinterpret_cast<const float4*>(A + (size_t)(bi + row) * D + dg);
        Ah[(dg >> 1) + 0][row] = __floats2half2_rn(v.x, v.y);
        Ah[(dg >> 1) + 1][row] = __floats2half2_rn(v.z, v.w);
    }
    // B tile: 64 rows x 32 d = 512 float4; 256 threads x 2.
    #pragma unroll
    for (int k = 0; k < 2; k++) {
        int idx = tid + k * 256;
        int row = idx & 63;
        int dg  = (idx >> 6) << 2;      // 0,4,...,28
        float4 v = *reinterpret_cast<const float4*>(B + (size_t)(bj + row) * D + dg);
        Bh[(dg >> 1) + 0][row] = __floats2half2_rn(v.x, v.y);
        Bh[(dg >> 1) + 1][row] = __floats2half2_rn(v.z, v.w);
    }
    __syncthreads();

    const int tx = tid & 15;            // 16 x 4 cols = 64
    const int ty = tid >> 4;            // 16 x 16 rows = 256
    const int ri = ty * 16;
    const int rj = tx * 4;

    // acc[i][j]: half2 running max (lo/hi = even/odd d-phase).
    __half2 acc[16][4];
    #pragma unroll
    for (int i = 0; i < 16; i++)
        #pragma unroll
        for (int j = 0; j < 4; j++)
            acc[i][j] = __float2half2_rn(0.0f);   // |diff| >= 0: safe identity

    #pragma unroll 4
    for (int dp = 0; dp < DP; dp++) {
        // A: 16 half2 = 64B = 4 LDS.128; 2 distinct addrs/warp (broadcast pairs).
        uint4 aq[4];
        aq[0] = *reinterpret_cast<const uint4*>(&Ah[dp][ri + 0]);
        aq[1] = *reinterpret_cast<const uint4*>(&Ah[dp][ri + 4]);
        aq[2] = *reinterpret_cast<const uint4*>(&Ah[dp][ri + 8]);
        aq[3] = *reinterpret_cast<const uint4*>(&Ah[dp][ri + 12]);
        // B: 4 half2 = 16B at 16B*tx -> 256B contiguous, conflict-free.
        uint4 bq = *reinterpret_cast<const uint4*>(&Bh[dp][rj]);

        // Alias loaded registers directly (no operand-copy MOVs).
        const __half2* ha = reinterpret_cast<const __half2*>(aq);
        const __half2* hb = reinterpret_cast<const __half2*>(&bq);

        #pragma unroll
        for (int i = 0; i < 16; i++)
            #pragma unroll
            for (int j = 0; j < 4; j++) {
                __half2 diff = __hsub2(ha[i], hb[j]);           // 2 d's
                acc[i][j] = __hmax2(acc[i][j], __habs2(diff));  // |.| folds
            }
    }

    // Epilogue: fold d-phases, store one float4 per row.
    #pragma unroll
    for (int i = 0; i < 16; i++) {
        float* po = out + (size_t)(bi + ri + i) * M + (bj + rj);
        float r0 = __half2float(__hmax(__low2half(acc[i][0]), __high2half(acc[i][0])));
        float r1 = __half2float(__hmax(__low2half(acc[i][1]), __high2half(acc[i][1])));
        float r2 = __half2float(__hmax(__low2half(acc[i][2]), __high2half(acc[i][2])));
        float r3 = __half2float(__hmax(__low2half(acc[i][3]), __high2half(acc[i][3])));
        *reinterpret_cast<float4*>(po) = make_float4(r0, r1, r2, r3);
    }
}

extern "C" void kernel_launch(void* const* d_in, const int* in_sizes, int n_in,
                              void* d_out, int out_size) {
    const float* A = (const float*)d_in[0];
    const float* B = (const float*)d_in[1];
    float* out = (float*)d_out;
    int N = in_sizes[0] / D;   // 4096
    int M = in_sizes[1] / D;   // 4096
    dim3 grid(M / TJ, N / TI);      // 64 x 16 = 1024 CTAs
    cheby_kernel<<<grid, 256>>>(A, B, out, M);
}

// round 15
// speedup vs baseline: 1.1967x; 1.0285x over previous
#include <cuda_runtime.h>
#include <cuda_fp16.h>

// Chebyshev (L-inf) pairwise distance: out[i,j] = max_d |A[i,d] - B[j,d]|
// A: [4096, 32] fp32, B: [4096, 32] fp32, out: [4096, 4096] fp32.
//
// R15 = R12 geometry x R14 codegen.
// Empirical law (14 rounds): dur = issued / (148 * IPC(occ)),
//   IPC ~2.74 @ 32 warps/SM, ~2.4 @ 16 warps/SM.
// 8x4 per-thread block (32 half2 accs) is the largest block fitting the
// 64-reg/thread budget that 32 warps/SM requires. Junk-instruction removal:
// direct uint4 aliasing (no operand-array rebuilds), unroll-8 dp loop
// (immediate LDS offsets), hoisted bases. Stream ~19.5M -> predict ~28us.

constexpr int D    = 32;
constexpr int DP   = D / 2;         // 16 d-pairs
constexpr int TILE = 128;
constexpr int RPAD = 132;           // half2 row stride (528B, 16B-aligned)

__global__ __launch_bounds__(512, 2)
void cheby_kernel(const float* __restrict__ A, const float* __restrict__ B,
                  float* __restrict__ out, int M) {
    __shared__ __half2 Ah[DP][RPAD];   // Ah[dp][r] = (A[bi+r][2dp], A[bi+r][2dp+1])
    __shared__ __half2 Bh[DP][RPAD];   // Bh[dp][c] = (B[bj+c][2dp], B[bj+c][2dp+1])

    const int tid = threadIdx.x;
    const int bi  = blockIdx.y * TILE;
    const int bj  = blockIdx.x * TILE;

    // Prologue: 1024 float4 per tile, 512 threads x 2 (proven in R12).
    #pragma unroll
    for (int k = 0; k < 2; k++) {
        int idx = tid + k * 512;
        int row = idx & 127;
        int dg  = (idx >> 7) << 2;       // 0,4,...,28
        float4 va = *reinterpret_cast<const float4*>(A + (size_t)(bi + row) * D + dg);
        Ah[(dg >> 1) + 0][row] = __floats2half2_rn(va.x, va.y);
        Ah[(dg >> 1) + 1][row] = __floats2half2_rn(va.z, va.w);
        float4 vb = *reinterpret_cast<const float4*>(B + (size_t)(bj + row) * D + dg);
        Bh[(dg >> 1) + 0][row] = __floats2half2_rn(vb.x, vb.y);
        Bh[(dg >> 1) + 1][row] = __floats2half2_rn(vb.z, vb.w);
    }
    __syncthreads();

    const int tx = tid & 31;            // 32 x 4 cols = 128
    const int ty = tid >> 5;            // 16 x 8 rows = 128
    const int ri = ty * 8;
    const int rj = tx * 4;

    // Hoisted smem bases; dp advances by an immediate multiple of RPAD.
    const __half2* aBase = &Ah[0][ri];
    const __half2* bBase = &Bh[0][rj];

    // acc[i][j]: half2 running max, lo/hi = even/odd d-phase.
    __half2 acc[8][4];
    #pragma unroll
    for (int i = 0; i < 8; i++)
        #pragma unroll
        for (int j = 0; j < 4; j++)
            acc[i][j] = __float2half2_rn(0.0f);   // |diff| >= 0: safe identity

    #pragma unroll 8
    for (int dp = 0; dp < DP; dp++) {
        // A: 8 half2 = 32B = 2 LDS.128, ONE address per warp (broadcast).
        uint4 aq0 = *reinterpret_cast<const uint4*>(aBase + dp * RPAD);
        uint4 aq1 = *reinterpret_cast<const uint4*>(aBase + dp * RPAD + 4);
        // B: 4 half2 = 16B at 16B*tx -> 512B contiguous per warp.
        uint4 bq  = *reinterpret_cast<const uint4*>(bBase + dp * RPAD);

        // Alias loaded registers directly -- no operand-copy MOVs.
        const __half2* ha0 = reinterpret_cast<const __half2*>(&aq0);
        const __half2* ha1 = reinterpret_cast<const __half2*>(&aq1);
        const __half2* hb  = reinterpret_cast<const __half2*>(&bq);

        #pragma unroll
        for (int i = 0; i < 4; i++)
            #pragma unroll
            for (int j = 0; j < 4; j++) {
                __half2 d0 = __hsub2(ha0[i], hb[j]);
                acc[i][j] = __hmax2(acc[i][j], __habs2(d0));
            }
        #pragma unroll
        for (int i = 0; i < 4; i++)
            #pragma unroll
            for (int j = 0; j < 4; j++) {
                __half2 d1 = __hsub2(ha1[i], hb[j]);
                acc[4 + i][j] = __hmax2(acc[4 + i][j], __habs2(d1));
            }
    }

    // Epilogue: fold the two d-phases, store fp32.
    #pragma unroll
    for (int i = 0; i < 8; i++) {
        float* po = out + (size_t)(bi + ri + i) * M + (bj + rj);
        float r0 = __half2float(__hmax(__low2half(acc[i][0]), __high2half(acc[i][0])));
        float r1 = __half2float(__hmax(__low2half(acc[i][1]), __high2half(acc[i][1])));
        float r2 = __half2float(__hmax(__low2half(acc[i][2]), __high2half(acc[i][2])));
        float r3 = __half2float(__hmax(__low2half(acc[i][3]), __high2half(acc[i][3])));
        *reinterpret_cast<float4*>(po) = make_float4(r0, r1, r2, r3);
    }
}

extern "C" void kernel_launch(void* const* d_in, const int* in_sizes, int n_in,
                              void* d_out, int out_size) {
    const float* A = (const float*)d_in[0];
    const float* B = (const float*)d_in[1];
    float* out = (float*)d_out;
    int N = in_sizes[0] / D;   // 4096
    int M = in_sizes[1] / D;   // 4096
    dim3 grid(M / TILE, N / TILE);  // 32 x 32 = 1024 CTAs
    cheby_kernel<<<grid, 512>>>(A, B, out, M);
}

// round 16
// speedup vs baseline: 1.2447x; 1.0402x over previous
#include <cuda_runtime.h>
#include <cuda_fp16.h>

// Chebyshev (L-inf) pairwise distance: out[i,j] = max_d |A[i,d] - B[j,d]|
// A: [4096, 32] fp32, B: [4096, 32] fp32, out: [4096, 4096] fp32.
//
// R16: SOFTWARE-PIPELINED fp16x2-over-d kernel. Diagnosis of the 33us
// plateau (R9/R12/R15): each warp stalls ~20 cyc per dp-iteration on the
// LDS->math scoreboard (3 loads, 29-cyc latency, then 32 dependent math).
// Fix: register double-buffering -- issue dp+1's 3 LDS before dp's math so
// the latency is hidden behind 32 issue slots of math.
// Costs +12 operand regs -> (256,3), 85-reg budget, 24 warps/SM.
// Geometry: 128x64 tile, 8x4 per-thread block (proven layouts: A broadcast,
// B 16B*tx contiguous, d-pair packing, fold epilogue).

constexpr int D  = 32;
constexpr int DP = D / 2;       // 16 d-pairs
constexpr int TI = 128;         // rows per CTA tile
constexpr int TJ = 64;          // cols per CTA tile
constexpr int AS = TI + 4;      // Ah row stride (132 half2 = 528B)
constexpr int BS = TJ + 4;      // Bh row stride (68 half2 = 272B)

__global__ __launch_bounds__(256, 3)
void cheby_kernel(const float* __restrict__ A, const float* __restrict__ B,
                  float* __restrict__ out, int M) {
    __shared__ __half2 Ah[DP][AS];  // Ah[dp][r] = (A[bi+r][2dp], A[bi+r][2dp+1])
    __shared__ __half2 Bh[DP][BS];  // Bh[dp][c] = (B[bj+c][2dp], B[bj+c][2dp+1])

    const int tid = threadIdx.x;
    const int bi  = blockIdx.y * TI;
    const int bj  = blockIdx.x * TJ;

    // A tile: 128 rows x 32 d = 1024 float4; 256 threads x 4.
    #pragma unroll
    for (int k = 0; k < 4; k++) {
        int idx = tid + k * 256;
        int row = idx & 127;
        int dg  = (idx >> 7) << 2;       // 0,4,...,28
        float4 v = *reinterpret_cast<const float4*>(A + (size_t)(bi + row) * D + dg);
        Ah[(dg >> 1) + 0][row] = __floats2half2_rn(v.x, v.y);
        Ah[(dg >> 1) + 1][row] = __floats2half2_rn(v.z, v.w);
    }
    // B tile: 64 rows x 32 d = 512 float4; 256 threads x 2.
    #pragma unroll
    for (int k = 0; k < 2; k++) {
        int idx = tid + k * 256;
        int row = idx & 63;
        int dg  = (idx >> 6) << 2;       // 0,4,...,28
        float4 v = *reinterpret_cast<const float4*>(B + (size_t)(bj + row) * D + dg);
        Bh[(dg >> 1) + 0][row] = __floats2half2_rn(v.x, v.y);
        Bh[(dg >> 1) + 1][row] = __floats2half2_rn(v.z, v.w);
    }
    __syncthreads();

    const int tx = tid & 15;            // 16 x 4 cols = 64
    const int ty = tid >> 4;            // 16 x 8 rows = 128
    const int ri = ty * 8;
    const int rj = tx * 4;

    const __half2* aBase = &Ah[0][ri];
    const __half2* bBase = &Bh[0][rj];

    __half2 acc[8][4];
    #pragma unroll
    for (int i = 0; i < 8; i++)
        #pragma unroll
        for (int j = 0; j < 4; j++)
            acc[i][j] = __float2half2_rn(0.0f);   // |diff| >= 0: safe identity

    // --- software pipeline: prime stage 0 ---
    uint4 a0 = *reinterpret_cast<const uint4*>(aBase);
    uint4 a1 = *reinterpret_cast<const uint4*>(aBase + 4);
    uint4 b0 = *reinterpret_cast<const uint4*>(bBase);

    #pragma unroll
    for (int dp = 0; dp < DP; dp++) {
        // Prefetch dp+1 operands BEFORE this iteration's math.
        uint4 na0, na1, nb0;
        if (dp + 1 < DP) {
            na0 = *reinterpret_cast<const uint4*>(aBase + (dp + 1) * AS);
            na1 = *reinterpret_cast<const uint4*>(aBase + (dp + 1) * AS + 4);
            nb0 = *reinterpret_cast<const uint4*>(bBase + (dp + 1) * BS);
        }

        const __half2* ha0 = reinterpret_cast<const __half2*>(&a0);
        const __half2* ha1 = reinterpret_cast<const __half2*>(&a1);
        const __half2* hb  = reinterpret_cast<const __half2*>(&b0);

        #pragma unroll
        for (int i = 0; i < 4; i++)
            #pragma unroll
            for (int j = 0; j < 4; j++) {
                __half2 df = __hsub2(ha0[i], hb[j]);
                acc[i][j] = __hmax2(acc[i][j], __habs2(df));
            }
        #pragma unroll
        for (int i = 0; i < 4; i++)
            #pragma unroll
            for (int j = 0; j < 4; j++) {
                __half2 df = __hsub2(ha1[i], hb[j]);
                acc[4 + i][j] = __hmax2(acc[4 + i][j], __habs2(df));
            }

        if (dp + 1 < DP) { a0 = na0; a1 = na1; b0 = nb0; }  // renamed away
    }

    // Epilogue: fold even/odd d-phases, store fp32 float4.
    #pragma unroll
    for (int i = 0; i < 8; i++) {
        float* po = out + (size_t)(bi + ri + i) * M + (bj + rj);
        float r0 = __half2float(__hmax(__low2half(acc[i][0]), __high2half(acc[i][0])));
        float r1 = __half2float(__hmax(__low2half(acc[i][1]), __high2half(acc[i][1])));
        float r2 = __half2float(__hmax(__low2half(acc[i][2]), __high2half(acc[i][2])));
        float r3 = __half2float(__hmax(__low2half(acc[i][3]), __high2half(acc[i][3])));
        *reinterpret_cast<float4*>(po) = make_float4(r0, r1, r2, r3);
    }
}

extern "C" void kernel_launch(void* const* d_in, const int* in_sizes, int n_in,
                              void* d_out, int out_size) {
    const float* A = (const float*)d_in[0];
    const float* B = (const float*)d_in[1];
    float* out = (float*)d_out;
    int N = in_sizes[0] / D;   // 4096
    int M = in_sizes[1] / D;   // 4096
    dim3 grid(M / TJ, N / TI);      // 64 x 32 = 2048 CTAs
    cheby_kernel<<<grid, 256>>>(A, B, out, M);
}

// round 17
// speedup vs baseline: 1.2519x; 1.0058x over previous
#include <cuda_runtime.h>
#include <cuda_fp16.h>

// Chebyshev (L-inf) pairwise distance: out[i,j] = max_d |A[i,d] - B[j,d]|
// A: [4096, 32] fp32, B: [4096, 32] fp32, out: [4096, 4096] fp32.
//
// R16: SOFTWARE-PIPELINED fp16x2-over-d kernel. Diagnosis of the 33us
// plateau (R9/R12/R15): each warp stalls ~20 cyc per dp-iteration on the
// LDS->math scoreboard (3 loads, 29-cyc latency, then 32 dependent math).
// Fix: register double-buffering -- issue dp+1's 3 LDS before dp's math so
// the latency is hidden behind 32 issue slots of math.
// Costs +12 operand regs -> (256,3), 85-reg budget, 24 warps/SM.
// Geometry: 128x64 tile, 8x4 per-thread block (proven layouts: A broadcast,
// B 16B*tx contiguous, d-pair packing, fold epilogue).

constexpr int D  = 32;
constexpr int DP = D / 2;       // 16 d-pairs
constexpr int TI = 128;         // rows per CTA tile
constexpr int TJ = 64;          // cols per CTA tile
constexpr int AS = TI + 4;      // Ah row stride (132 half2 = 528B)
constexpr int BS = TJ + 4;      // Bh row stride (68 half2 = 272B)

__global__ __launch_bounds__(256, 3)
void cheby_kernel(const float* __restrict__ A, const float* __restrict__ B,
                  float* __restrict__ out, int M) {
    __shared__ __half2 Ah[DP][AS];  // Ah[dp][r] = (A[bi+r][2dp], A[bi+r][2dp+1])
    __shared__ __half2 Bh[DP][BS];  // Bh[dp][c] = (B[bj+c][2dp], B[bj+c][2dp+1])

    const int tid = threadIdx.x;
    const int bi  = blockIdx.y * TI;
    const int bj  = blockIdx.x * TJ;

    // A tile: 128 rows x 32 d = 1024 float4; 256 threads x 4.
    #pragma unroll
    for (int k = 0; k < 4; k++) {
        int idx = tid + k * 256;
        int row = idx & 127;
        int dg  = (idx >> 7) << 2;       // 0,4,...,28
        float4 v = *reinterpret_cast<const float4*>(A + (size_t)(bi + row) * D + dg);
        Ah[(dg >> 1) + 0][row] = __floats2half2_rn(v.x, v.y);
        Ah[(dg >> 1) + 1][row] = __floats2half2_rn(v.z, v.w);
    }
    // B tile: 64 rows x 32 d = 512 float4; 256 threads x 2.
    #pragma unroll
    for (int k = 0; k < 2; k++) {
        int idx = tid + k * 256;
        int row = idx & 63;
        int dg  = (idx >> 6) << 2;       // 0,4,...,28
        float4 v = *reinterpret_cast<const float4*>(B + (size_t)(bj + row) * D + dg);
        Bh[(dg >> 1) + 0][row] = __floats2half2_rn(v.x, v.y);
        Bh[(dg >> 1) + 1][row] = __floats2half2_rn(v.z, v.w);
    }
    __syncthreads();

    const int tx = tid & 15;            // 16 x 4 cols = 64
    const int ty = tid >> 4;            // 16 x 8 rows = 128
    const int ri = ty * 8;
    const int rj = tx * 4;

    const __half2* aBase = &Ah[0][ri];
    const __half2* bBase = &Bh[0][rj];

    __half2 acc[8][4];
    #pragma unroll
    for (int i = 0; i < 8; i++)
        #pragma unroll
        for (int j = 0; j < 4; j++)
            acc[i][j] = __float2half2_rn(0.0f);   // |diff| >= 0: safe identity

    // --- software pipeline: prime stage 0 ---
    uint4 a0 = *reinterpret_cast<const uint4*>(aBase);
    uint4 a1 = *reinterpret_cast<const uint4*>(aBase + 4);
    uint4 b0 = *reinterpret_cast<const uint4*>(bBase);

    #pragma unroll
    for (int dp = 0; dp < DP; dp++) {
        // Prefetch dp+1 operands BEFORE this iteration's math.
        uint4 na0, na1, nb0;
        if (dp + 1 < DP) {
            na0 = *reinterpret_cast<const uint4*>(aBase + (dp + 1) * AS);
            na1 = *reinterpret_cast<const uint4*>(aBase + (dp + 1) * AS + 4);
            nb0 = *reinterpret_cast<const uint4*>(bBase + (dp + 1) * BS);
        }

        const __half2* ha0 = reinterpret_cast<const __half2*>(&a0);
        const __half2* ha1 = reinterpret_cast<const __half2*>(&a1);
        const __half2* hb  = reinterpret_cast<const __half2*>(&b0);

        #pragma unroll
        for (int i = 0; i < 4; i++)
            #pragma unroll
            for (int j = 0; j < 4; j++) {
                __half2 df = __hsub2(ha0[i], hb[j]);
                acc[i][j] = __hmax2(acc[i][j], __habs2(df));
            }
        #pragma unroll
        for (int i = 0; i < 4; i++)
            #pragma unroll
            for (int j = 0; j < 4; j++) {
                __half2 df = __hsub2(ha1[i], hb[j]);
                acc[4 + i][j] = __hmax2(acc[4 + i][j], __habs2(df));
            }

        if (dp + 1 < DP) { a0 = na0; a1 = na1; b0 = nb0; }  // renamed away
    }

    // Epilogue: fold even/odd d-phases, store fp32 float4.
    #pragma unroll
    for (int i = 0; i < 8; i++) {
        float* po = out + (size_t)(bi + ri + i) * M + (bj + rj);
        float r0 = __half2float(__hmax(__low2half(acc[i][0]), __high2half(acc[i][0])));
        float r1 = __half2float(__hmax(__low2half(acc[i][1]), __high2half(acc[i][1])));
        float r2 = __half2float(__hmax(__low2half(acc[i][2]), __high2half(acc[i][2])));
        float r3 = __half2float(__hmax(__low2half(acc[i][3]), __high2half(acc[i][3])));
        *reinterpret_cast<float4*>(po) = make_float4(r0, r1, r2, r3);
    }
}

extern "C" void kernel_launch(void* const* d_in, const int* in_sizes, int n_in,
                              void* d_out, int out_size) {
    const float* A = (const float*)d_in[0];
    const float* B = (const float*)d_in[1];
    float* out = (float*)d_out;
    int N = in_sizes[0] / D;   // 4096
    int M = in_sizes[1] / D;   // 4096
    dim3 grid(M / TJ, N / TI);      // 64 x 32 = 2048 CTAs
    cheby_kernel<<<grid, 256>>>(A, B, out, M);
}